// round 2
// baseline (speedup 1.0000x reference)
#include <cuda_runtime.h>
#include <cuda_bf16.h>
#include <math.h>

// Problem constants
#define B_  8
#define C_  256
#define CR_ 32
#define H_  64
#define W_  64
#define HW_ (H_*W_)
#define NPIX (B_*HW_)          // 32768
#define NOUT 320               // q(32) | k(32) | v(256)

// Scratch for projected q|k|v, pixel-major: g_qkv[pix*320 + n]
__device__ float g_qkv[(size_t)NPIX * NOUT];

// ---------------------------------------------------------------------------
// Kernel 1: fused QKV projection GEMM.
//   out[pix][n] = sum_c x[b][c][hw] * W[n][c] + bias[n]
//   M = 32768, N = 320, K = 256.  BM=128, BN=64, BK=32, 256 threads, TM=8 TN=4.
// ---------------------------------------------------------------------------
__global__ __launch_bounds__(256)
void qkv_gemm_kernel(const float* __restrict__ x,
                     const float* __restrict__ Wq, const float* __restrict__ bq,
                     const float* __restrict__ Wk, const float* __restrict__ bk,
                     const float* __restrict__ Wv, const float* __restrict__ bv)
{
    __shared__ float As[32][128];     // [k][m]
    __shared__ float Bs[32][68];      // [k][n], padded

    const int tid  = threadIdx.x;
    const int nblk = blockIdx.x;      // 0..4
    const int mblk = blockIdx.y;      // 0..255

    const int pix0 = mblk * 128;              // whole tile within one batch image
    const int b    = pix0 >> 12;              // /4096
    const int hw0  = pix0 & 4095;
    const size_t xbase = (size_t)b * C_ * HW_ + hw0;

    const int mb = (tid >> 4) * 8;            // 0..120
    const int nb = (tid & 15) * 4;            // 0..60

    float acc[8][4];
    #pragma unroll
    for (int i = 0; i < 8; i++)
        #pragma unroll
        for (int j = 0; j < 4; j++) acc[i][j] = 0.f;

    for (int k0 = 0; k0 < C_; k0 += 32) {
        // Load A tile: 32 rows of 128 contiguous pixels (float4, coalesced)
        #pragma unroll
        for (int q = 0; q < 4; q++) {
            int f  = tid + q * 256;           // 0..1023 float4 units
            int kk = f >> 5;                  // 0..31
            int m4 = (f & 31) * 4;
            float4 v = *(const float4*)(x + xbase + (size_t)(k0 + kk) * HW_ + m4);
            *(float4*)(&As[kk][m4]) = v;
        }
        // Load B tile: W[n][k0..k0+31], transposed into Bs[k][n]
        #pragma unroll
        for (int q = 0; q < 2; q++) {
            int f  = tid + q * 256;           // 0..511 float4 units
            int n  = f >> 3;                  // 0..63
            int kq = (f & 7) * 4;
            int ng = nblk * 64 + n;
            const float* Wrow = (ng < 32) ? (Wq + ng * C_)
                              : (ng < 64) ? (Wk + (ng - 32) * C_)
                                          : (Wv + (ng - 64) * C_);
            float4 wv = *(const float4*)(Wrow + k0 + kq);
            Bs[kq + 0][n] = wv.x;
            Bs[kq + 1][n] = wv.y;
            Bs[kq + 2][n] = wv.z;
            Bs[kq + 3][n] = wv.w;
        }
        __syncthreads();

        #pragma unroll
        for (int kk = 0; kk < 32; kk++) {
            float4 a0 = *(const float4*)(&As[kk][mb]);
            float4 a1 = *(const float4*)(&As[kk][mb + 4]);
            float4 bb = *(const float4*)(&Bs[kk][nb]);
            float am[8] = {a0.x, a0.y, a0.z, a0.w, a1.x, a1.y, a1.z, a1.w};
            float bn[4] = {bb.x, bb.y, bb.z, bb.w};
            #pragma unroll
            for (int i = 0; i < 8; i++)
                #pragma unroll
                for (int j = 0; j < 4; j++)
                    acc[i][j] = fmaf(am[i], bn[j], acc[i][j]);
        }
        __syncthreads();
    }

    // Bias + store
    float bias[4];
    #pragma unroll
    for (int j = 0; j < 4; j++) {
        int ng = nblk * 64 + nb + j;
        bias[j] = (ng < 32) ? bq[ng] : (ng < 64) ? bk[ng - 32] : bv[ng - 64];
    }
    #pragma unroll
    for (int i = 0; i < 8; i++) {
        size_t row = (size_t)(pix0 + mb + i) * NOUT + nblk * 64 + nb;
        float4 o;
        o.x = acc[i][0] + bias[0];
        o.y = acc[i][1] + bias[1];
        o.z = acc[i][2] + bias[2];
        o.w = acc[i][3] + bias[3];
        *(float4*)(&g_qkv[row]) = o;
    }
}

// ---------------------------------------------------------------------------
// Kernel 2: local 3x3 window attention + residual.
//   One block: 32-pixel row segment (b, h, wbase..wbase+31). 256 threads.
//   Phase 1: energies from q & k halo (zero-padded -> energy exactly 0 OOB,
//            matching the reference's zero-padded unfold inside softmax).
//   Phase 2: softmax over all 9 window slots.
//   Phase 3: weighted v accumulation in 4 channel chunks of 64; out = g*o + x.
// ---------------------------------------------------------------------------
#define PTILE 32
#define KCOLS 34          // PTILE + 2 halo
#define CPAD  65          // 64-channel chunk padded to 65 (conflict-free)

__global__ __launch_bounds__(256)
void attn_kernel(const float* __restrict__ x,
                 const float* __restrict__ gamma,
                 float* __restrict__ out)
{
    // smem reused: phase1 {sq | sk}, phase3 {sv}
    __shared__ float smem[3 * KCOLS * CPAD];          // 6630 floats (covers 4422 too)
    __shared__ float se[PTILE * 9];                   // attention weights

    float* sq = smem;                                 // [32][33]
    float* sk = smem + PTILE * 33;                    // [3][34][33]
    float* sv = smem;                                 // [3][34][65]

    const int tid   = threadIdx.x;
    const int b     = blockIdx.y;
    const int h     = blockIdx.x >> 1;
    const int wbase = (blockIdx.x & 1) * PTILE;
    const int pixrow = b * HW_ + h * W_;              // pixel index of (b,h,0)
    const float g0 = gamma[0];

    // ---- Phase 1a: load q tile ----
    for (int idx = tid; idx < PTILE * 32; idx += 256) {
        int p = idx >> 5, c = idx & 31;
        sq[p * 33 + c] = g_qkv[(size_t)(pixrow + wbase + p) * NOUT + c];
    }
    // ---- Phase 1b: load k halo (zero padded) ----
    for (int idx = tid; idx < 3 * KCOLS * 32; idx += 256) {
        int c    = idx & 31;
        int rest = idx >> 5;
        int col  = rest % KCOLS;
        int r    = rest / KCOLS;
        int hh   = h + r - 1;
        int ww   = wbase + col - 1;
        float v = 0.f;
        if (hh >= 0 && hh < H_ && ww >= 0 && ww < W_)
            v = g_qkv[(size_t)(b * HW_ + hh * W_ + ww) * NOUT + 32 + c];
        sk[(r * KCOLS + col) * 33 + c] = v;
    }
    __syncthreads();

    // ---- Phase 1c: energies (288 tasks: 32 pixels x 9 slots) ----
    for (int task = tid; task < PTILE * 9; task += 256) {
        int p = task / 9, j = task % 9;
        int r = j / 3, dx = j % 3;
        const float* qp = sq + p * 33;
        const float* kp = sk + (r * KCOLS + p + dx) * 33;
        float e = 0.f;
        #pragma unroll
        for (int c = 0; c < 32; c++) e = fmaf(qp[c], kp[c], e);
        se[p * 9 + j] = e;
    }
    __syncthreads();

    // ---- Phase 2: softmax over 9 (zeros from OOB stay in the denominator) ----
    if (tid < PTILE) {
        float e[9], m = -1e30f;
        #pragma unroll
        for (int j = 0; j < 9; j++) { e[j] = se[tid * 9 + j]; m = fmaxf(m, e[j]); }
        float s = 0.f;
        #pragma unroll
        for (int j = 0; j < 9; j++) { e[j] = expf(e[j] - m); s += e[j]; }
        float inv = 1.f / s;
        #pragma unroll
        for (int j = 0; j < 9; j++) se[tid * 9 + j] = e[j] * inv;
    }
    __syncthreads();

    // ---- Phase 3: v accumulation, 4 channel chunks of 64 ----
    const int p  = tid & 31;
    const int cg = tid >> 5;          // 0..7 -> channels cg*8 .. cg*8+7
    float a[9];
    #pragma unroll
    for (int j = 0; j < 9; j++) a[j] = se[p * 9 + j];

    int basej[9];
    #pragma unroll
    for (int j = 0; j < 9; j++)
        basej[j] = ((j / 3) * KCOLS + p + (j % 3)) * CPAD + cg * 8;

    for (int c0 = 0; c0 < C_; c0 += 64) {
        __syncthreads();   // protect smem reuse (prev reads done before overwrite)
        // load v halo chunk (float4 global loads, scalar smem stores)
        for (int idx = tid; idx < 3 * KCOLS * 16; idx += 256) {
            int c4   = idx & 15;
            int rest = idx >> 4;
            int col  = rest % KCOLS;
            int r    = rest / KCOLS;
            int hh   = h + r - 1;
            int ww   = wbase + col - 1;
            float4 v = make_float4(0.f, 0.f, 0.f, 0.f);
            if (hh >= 0 && hh < H_ && ww >= 0 && ww < W_)
                v = *(const float4*)(&g_qkv[(size_t)(b * HW_ + hh * W_ + ww) * NOUT
                                            + 64 + c0 + c4 * 4]);
            float* d = &sv[(r * KCOLS + col) * CPAD + c4 * 4];
            d[0] = v.x; d[1] = v.y; d[2] = v.z; d[3] = v.w;
        }
        __syncthreads();

        float acc[8];
        #pragma unroll
        for (int i = 0; i < 8; i++) acc[i] = 0.f;
        #pragma unroll
        for (int j = 0; j < 9; j++) {
            const float* svp = sv + basej[j];
            float aj = a[j];
            #pragma unroll
            for (int i = 0; i < 8; i++) acc[i] = fmaf(aj, svp[i], acc[i]);
        }

        // out = gamma*o + x   (coalesced: lanes sweep p along w)
        #pragma unroll
        for (int i = 0; i < 8; i++) {
            int cglob = c0 + cg * 8 + i;
            size_t xi = ((size_t)(b * C_ + cglob)) * HW_ + h * W_ + wbase + p;
            out[xi] = fmaf(g0, acc[i], x[xi]);
        }
    }
}

// ---------------------------------------------------------------------------
extern "C" void kernel_launch(void* const* d_in, const int* in_sizes, int n_in,
                              void* d_out, int out_size)
{
    const float* x     = (const float*)d_in[0];
    const float* Wq    = (const float*)d_in[1];
    const float* bq    = (const float*)d_in[2];
    const float* Wk    = (const float*)d_in[3];
    const float* bk    = (const float*)d_in[4];
    const float* Wv    = (const float*)d_in[5];
    const float* bv    = (const float*)d_in[6];
    const float* gamma = (const float*)d_in[7];
    float* out = (float*)d_out;

    dim3 ggrid(NOUT / 64, NPIX / 128);     // (5, 256)
    qkv_gemm_kernel<<<ggrid, 256>>>(x, Wq, bq, Wk, bk, Wv, bv);

    dim3 agrid(H_ * 2, B_);                // (128, 8)
    attn_kernel<<<agrid, 256>>>(x, gamma, out);
}

// round 5
// speedup vs baseline: 1.6013x; 1.6013x over previous
#include <cuda_runtime.h>
#include <cuda_bf16.h>
#include <math.h>
#include <stdint.h>

// Problem constants
#define B_  8
#define C_  256
#define H_  64
#define W_  64
#define HW_ 4096
#define NPIX 32768
#define NOUT 320               // q(32) | k(32) | v(256)

// Scratch
__device__ float g_qkv[(size_t)NPIX * NOUT];     // fp32 pixel-major qkv (attn input)
__device__ uint4 g_xt4[(size_t)NPIX * 32];       // bf16 x, pixel-major: [pix][256ch] = 32 uint4/row
__device__ uint4 g_wb4[320 * 32];                // bf16 W, [n][256ch], n-order q|k|v

#define SWZ(o) ((o) ^ (((o) >> 3) & 0x70))

__device__ __forceinline__ uint32_t pack_bf16(float lo, float hi) {
    uint32_t l = (uint32_t)__bfloat16_as_ushort(__float2bfloat16_rn(lo));
    uint32_t h = (uint32_t)__bfloat16_as_ushort(__float2bfloat16_rn(hi));
    return (h << 16) | l;
}

__device__ __forceinline__ void cp16(uint32_t dst, const void* src) {
    asm volatile("cp.async.cg.shared.global [%0], [%1], 16;" :: "r"(dst), "l"(src) : "memory");
}

// ---------------------------------------------------------------------------
// Kernel 0: prep. blocks 0..1023: transpose+convert x -> g_xt4 (bf16 pixel-major).
//           block 1024: convert W -> g_wb4.
// ---------------------------------------------------------------------------
__global__ __launch_bounds__(256)
void prep_kernel(const float* __restrict__ x,
                 const float* __restrict__ Wq, const float* __restrict__ Wk,
                 const float* __restrict__ Wv)
{
    if (blockIdx.x == 1024) {
        for (int idx = threadIdx.x; idx < 320 * 32; idx += 256) {
            int n = idx >> 5, cg = idx & 31;
            const float* row = (n < 32) ? Wq + n * C_
                             : (n < 64) ? Wk + (n - 32) * C_
                                        : Wv + (n - 64) * C_;
            const float* p = row + cg * 8;
            uint4 o;
            o.x = pack_bf16(p[0], p[1]); o.y = pack_bf16(p[2], p[3]);
            o.z = pack_bf16(p[4], p[5]); o.w = pack_bf16(p[6], p[7]);
            g_wb4[idx] = o;
        }
        return;
    }
    __shared__ float s[256][33];
    const int tid  = threadIdx.x;
    const int pix0 = blockIdx.x * 32;
    const int b    = pix0 >> 12;
    const int hw0  = pix0 & 4095;
    const float4* x4 = (const float4*)x;
    #pragma unroll
    for (int it = 0; it < 8; ++it) {
        int idx = it * 256 + tid;
        int c = idx >> 3, q = idx & 7;
        float4 v = x4[((size_t)(b * 256 + c)) * 1024 + (hw0 >> 2) + q];
        s[c][q * 4 + 0] = v.x; s[c][q * 4 + 1] = v.y;
        s[c][q * 4 + 2] = v.z; s[c][q * 4 + 3] = v.w;
    }
    __syncthreads();
    #pragma unroll
    for (int it = 0; it < 4; ++it) {
        int idx = it * 256 + tid;
        int p = idx >> 5, cg = idx & 31;
        int c0 = cg * 8;
        uint4 o;
        o.x = pack_bf16(s[c0 + 0][p], s[c0 + 1][p]);
        o.y = pack_bf16(s[c0 + 2][p], s[c0 + 3][p]);
        o.z = pack_bf16(s[c0 + 4][p], s[c0 + 5][p]);
        o.w = pack_bf16(s[c0 + 6][p], s[c0 + 7][p]);
        g_xt4[(size_t)(pix0 + p) * 32 + cg] = o;
    }
}

// ---------------------------------------------------------------------------
// Kernel 1: QKV projection via bf16 mma.sync (HMMA).
//   CTA = 128-pixel M-tile x full N=320 (5 chunks of 64). K=256 resident in smem.
//   A: 128x256 bf16 (64KB) as 4 k-chunks of [128 rows][128B] SW128-swizzled.
//   B: double-buffered 64x256 chunks (2x32KB), cp.async prefetch overlaps MMA.
//   8 warps in 4x2 grid, warp tile 32x32, mma.m16n8k16 row.col f32.bf16.
// ---------------------------------------------------------------------------
#define GEMM_SMEM 132096   // 64KB A + 2x32KB B + 1KB align slack

__global__ __launch_bounds__(256)
void qkv_mma_gemm(const float* __restrict__ bq, const float* __restrict__ bk,
                  const float* __restrict__ bv)
{
    extern __shared__ unsigned char dsm[];
    __shared__ float sbias[320];

    const int tid  = threadIdx.x;
    const int lane = tid & 31;
    const int wid  = tid >> 5;
    const int wm   = wid >> 1;          // 0..3 (M)
    const int wn   = wid & 1;           // 0..1 (N)
    const int pix0 = blockIdx.x * 128;

    unsigned char* base = (unsigned char*)(((uintptr_t)dsm + 1023) & ~(uintptr_t)1023);
    const uint32_t As_u = (uint32_t)__cvta_generic_to_shared(base);
    const uint32_t Bs_u = As_u + 65536;

    for (int i = tid; i < 320; i += 256)
        sbias[i] = (i < 32) ? bq[i] : (i < 64) ? bk[i - 32] : bv[i - 64];

    // Issue A (128 rows x 32 uint4) + B chunk 0 (64 x 32 uint4) via cp.async.
    {
        const uint4* src = g_xt4 + (size_t)pix0 * 32;
        #pragma unroll
        for (int it = 0; it < 16; ++it) {
            int u = it * 256 + tid;
            int p = u >> 5, g = u & 31;
            cp16(As_u + (g >> 3) * 16384 + SWZ(p * 128 + (g & 7) * 16), src + u);
        }
        #pragma unroll
        for (int it = 0; it < 8; ++it) {
            int u = it * 256 + tid;
            int n = u >> 5, g = u & 31;
            cp16(Bs_u + (g >> 3) * 8192 + SWZ(n * 128 + (g & 7) * 16), g_wb4 + u);
        }
    }
    asm volatile("cp.async.commit_group;" ::: "memory");
    asm volatile("cp.async.wait_group 0;" ::: "memory");
    __syncthreads();

    // Precompute ldmatrix lane-address components
    const int a_row  = (lane & 15);          // row within 16-row tile
    const int a_koff = (lane >> 4) << 4;     // 0 or 16 bytes
    const int b_r    = (lane & 7);
    const int b_grp  = lane >> 3;            // 0..3
    const int b_nrow = ((b_grp >> 1) << 3) + b_r;   // 0..15 within n16 pair
    const int b_koff = (b_grp & 1) << 4;            // 0 or 16 bytes

    for (int nc = 0; nc < 5; ++nc) {
        if (nc < 4) {   // prefetch next B chunk into other buffer
            const uint4* src = g_wb4 + (size_t)(nc + 1) * 64 * 32;
            uint32_t bb = Bs_u + ((nc + 1) & 1) * 32768;
            #pragma unroll
            for (int it = 0; it < 8; ++it) {
                int u = it * 256 + tid;
                int n = u >> 5, g = u & 31;
                cp16(bb + (g >> 3) * 8192 + SWZ(n * 128 + (g & 7) * 16), src + u);
            }
            asm volatile("cp.async.commit_group;" ::: "memory");
        }
        const uint32_t Bcur = Bs_u + (nc & 1) * 32768;

        float acc[2][4][4];
        #pragma unroll
        for (int mi = 0; mi < 2; mi++)
            #pragma unroll
            for (int nj = 0; nj < 4; nj++)
                #pragma unroll
                for (int q = 0; q < 4; q++) acc[mi][nj][q] = 0.f;

        #pragma unroll
        for (int kt = 0; kt < 16; ++kt) {
            const int chunk = kt >> 2;
            const int kb    = (kt & 3) * 32;

            uint32_t af[2][4];
            #pragma unroll
            for (int mi = 0; mi < 2; mi++) {
                int row = wm * 32 + mi * 16 + a_row;
                uint32_t ad = As_u + chunk * 16384 + SWZ(row * 128 + kb + a_koff);
                asm volatile("ldmatrix.sync.aligned.m8n8.x4.shared.b16 {%0,%1,%2,%3}, [%4];"
                             : "=r"(af[mi][0]), "=r"(af[mi][1]), "=r"(af[mi][2]), "=r"(af[mi][3])
                             : "r"(ad));
            }
            uint32_t bf[2][4];   // [njp][t]: t0,t1 = n-tile(2*njp); t2,t3 = n-tile(2*njp+1)
            #pragma unroll
            for (int njp = 0; njp < 2; njp++) {
                int n = wn * 32 + njp * 16 + b_nrow;
                uint32_t bd = Bcur + chunk * 8192 + SWZ(n * 128 + kb + b_koff);
                asm volatile("ldmatrix.sync.aligned.m8n8.x4.shared.b16 {%0,%1,%2,%3}, [%4];"
                             : "=r"(bf[njp][0]), "=r"(bf[njp][1]), "=r"(bf[njp][2]), "=r"(bf[njp][3])
                             : "r"(bd));
            }
            #pragma unroll
            for (int mi = 0; mi < 2; mi++)
                #pragma unroll
                for (int nj = 0; nj < 4; nj++) {
                    uint32_t b0 = bf[nj >> 1][(nj & 1) * 2 + 0];
                    uint32_t b1 = bf[nj >> 1][(nj & 1) * 2 + 1];
                    asm volatile(
                        "mma.sync.aligned.m16n8k16.row.col.f32.bf16.bf16.f32 "
                        "{%0,%1,%2,%3}, {%4,%5,%6,%7}, {%8,%9}, {%0,%1,%2,%3};"
                        : "+f"(acc[mi][nj][0]), "+f"(acc[mi][nj][1]),
                          "+f"(acc[mi][nj][2]), "+f"(acc[mi][nj][3])
                        : "r"(af[mi][0]), "r"(af[mi][1]), "r"(af[mi][2]), "r"(af[mi][3]),
                          "r"(b0), "r"(b1));
                }
        }

        // Epilogue for this N-chunk: +bias, fp32 store to g_qkv (pixel-major)
        {
            const int colq = (lane & 3) * 2;
            const int rowq = lane >> 2;
            #pragma unroll
            for (int mi = 0; mi < 2; mi++) {
                int r0 = pix0 + wm * 32 + mi * 16 + rowq;
                #pragma unroll
                for (int nj = 0; nj < 4; nj++) {
                    int col = nc * 64 + wn * 32 + nj * 8 + colq;
                    float bs0 = sbias[col], bs1 = sbias[col + 1];
                    float2 s0 = make_float2(acc[mi][nj][0] + bs0, acc[mi][nj][1] + bs1);
                    float2 s1 = make_float2(acc[mi][nj][2] + bs0, acc[mi][nj][3] + bs1);
                    *(float2*)(g_qkv + (size_t)r0 * NOUT + col)       = s0;
                    *(float2*)(g_qkv + (size_t)(r0 + 8) * NOUT + col) = s1;
                }
            }
        }

        if (nc < 4) {
            asm volatile("cp.async.wait_group 0;" ::: "memory");
            __syncthreads();
        }
    }
}

// ---------------------------------------------------------------------------
// Kernel 2: local 3x3 window attention + residual (unchanged, known-good).
// ---------------------------------------------------------------------------
#define PTILE 32
#define KCOLS 34
#define CPAD  65

__global__ __launch_bounds__(256)
void attn_kernel(const float* __restrict__ x,
                 const float* __restrict__ gamma,
                 float* __restrict__ out)
{
    __shared__ float smem[3 * KCOLS * CPAD];
    __shared__ float se[PTILE * 9];

    float* sq = smem;
    float* sk = smem + PTILE * 33;
    float* sv = smem;

    const int tid   = threadIdx.x;
    const int b     = blockIdx.y;
    const int h     = blockIdx.x >> 1;
    const int wbase = (blockIdx.x & 1) * PTILE;
    const int pixrow = b * HW_ + h * W_;
    const float g0 = gamma[0];

    for (int idx = tid; idx < PTILE * 32; idx += 256) {
        int p = idx >> 5, c = idx & 31;
        sq[p * 33 + c] = g_qkv[(size_t)(pixrow + wbase + p) * NOUT + c];
    }
    for (int idx = tid; idx < 3 * KCOLS * 32; idx += 256) {
        int c    = idx & 31;
        int rest = idx >> 5;
        int col  = rest % KCOLS;
        int r    = rest / KCOLS;
        int hh   = h + r - 1;
        int ww   = wbase + col - 1;
        float v = 0.f;
        if (hh >= 0 && hh < H_ && ww >= 0 && ww < W_)
            v = g_qkv[(size_t)(b * HW_ + hh * W_ + ww) * NOUT + 32 + c];
        sk[(r * KCOLS + col) * 33 + c] = v;
    }
    __syncthreads();

    for (int task = tid; task < PTILE * 9; task += 256) {
        int p = task / 9, j = task % 9;
        int r = j / 3, dx = j % 3;
        const float* qp = sq + p * 33;
        const float* kp = sk + (r * KCOLS + p + dx) * 33;
        float e = 0.f;
        #pragma unroll
        for (int c = 0; c < 32; c++) e = fmaf(qp[c], kp[c], e);
        se[p * 9 + j] = e;
    }
    __syncthreads();

    if (tid < PTILE) {
        float e[9], m = -1e30f;
        #pragma unroll
        for (int j = 0; j < 9; j++) { e[j] = se[tid * 9 + j]; m = fmaxf(m, e[j]); }
        float s = 0.f;
        #pragma unroll
        for (int j = 0; j < 9; j++) { e[j] = expf(e[j] - m); s += e[j]; }
        float inv = 1.f / s;
        #pragma unroll
        for (int j = 0; j < 9; j++) se[tid * 9 + j] = e[j] * inv;
    }
    __syncthreads();

    const int p  = tid & 31;
    const int cg = tid >> 5;
    float a[9];
    #pragma unroll
    for (int j = 0; j < 9; j++) a[j] = se[p * 9 + j];

    int basej[9];
    #pragma unroll
    for (int j = 0; j < 9; j++)
        basej[j] = ((j / 3) * KCOLS + p + (j % 3)) * CPAD + cg * 8;

    for (int c0 = 0; c0 < C_; c0 += 64) {
        __syncthreads();
        for (int idx = tid; idx < 3 * KCOLS * 16; idx += 256) {
            int c4   = idx & 15;
            int rest = idx >> 4;
            int col  = rest % KCOLS;
            int r    = rest / KCOLS;
            int hh   = h + r - 1;
            int ww   = wbase + col - 1;
            float4 v = make_float4(0.f, 0.f, 0.f, 0.f);
            if (hh >= 0 && hh < H_ && ww >= 0 && ww < W_)
                v = *(const float4*)(&g_qkv[(size_t)(b * HW_ + hh * W_ + ww) * NOUT
                                            + 64 + c0 + c4 * 4]);
            float* d = &sv[(r * KCOLS + col) * CPAD + c4 * 4];
            d[0] = v.x; d[1] = v.y; d[2] = v.z; d[3] = v.w;
        }
        __syncthreads();

        float acc[8];
        #pragma unroll
        for (int i = 0; i < 8; i++) acc[i] = 0.f;
        #pragma unroll
        for (int j = 0; j < 9; j++) {
            const float* svp = sv + basej[j];
            float aj = a[j];
            #pragma unroll
            for (int i = 0; i < 8; i++) acc[i] = fmaf(aj, svp[i], acc[i]);
        }

        #pragma unroll
        for (int i = 0; i < 8; i++) {
            int cglob = c0 + cg * 8 + i;
            size_t xi = ((size_t)(b * C_ + cglob)) * HW_ + h * W_ + wbase + p;
            out[xi] = fmaf(g0, acc[i], x[xi]);
        }
    }
}

// ---------------------------------------------------------------------------
extern "C" void kernel_launch(void* const* d_in, const int* in_sizes, int n_in,
                              void* d_out, int out_size)
{
    const float* x     = (const float*)d_in[0];
    const float* Wq    = (const float*)d_in[1];
    const float* bq    = (const float*)d_in[2];
    const float* Wk    = (const float*)d_in[3];
    const float* bk    = (const float*)d_in[4];
    const float* Wv    = (const float*)d_in[5];
    const float* bv    = (const float*)d_in[6];
    const float* gamma = (const float*)d_in[7];
    float* out = (float*)d_out;

    cudaFuncSetAttribute(qkv_mma_gemm, cudaFuncAttributeMaxDynamicSharedMemorySize, GEMM_SMEM);

    prep_kernel<<<1025, 256>>>(x, Wq, Wk, Wv);
    qkv_mma_gemm<<<256, 256, GEMM_SMEM>>>(bq, bk, bv);

    dim3 agrid(H_ * 2, B_);
    attn_kernel<<<agrid, 256>>>(x, gamma, out);
}

// round 6
// speedup vs baseline: 2.6291x; 1.6419x over previous
#include <cuda_runtime.h>
#include <cuda_bf16.h>
#include <math.h>
#include <stdint.h>

// Problem constants
#define B_  8
#define C_  256
#define H_  64
#define W_  64
#define HW_ 4096
#define NPIX 32768

// Scratch
__device__ float    g_qk[(size_t)NPIX * 64];     // fp32 q(32)|k(32), pixel-major
__device__ uint32_t g_vb[(size_t)NPIX * 128];    // bf16x2 v (256ch), pixel-major
__device__ uint4    g_wb4[320 * 32];             // bf16 W, [n][256ch], n-order q|k|v

#define SWZ(o) ((o) ^ (((o) >> 3) & 0x70))

__device__ __forceinline__ uint32_t pack_bf16(float lo, float hi) {
    uint32_t l = (uint32_t)__bfloat16_as_ushort(__float2bfloat16_rn(lo));
    uint32_t h = (uint32_t)__bfloat16_as_ushort(__float2bfloat16_rn(hi));
    return (h << 16) | l;
}

__device__ __forceinline__ void cp16(uint32_t dst, const void* src) {
    asm volatile("cp.async.cg.shared.global [%0], [%1], 16;" :: "r"(dst), "l"(src) : "memory");
}

// ---------------------------------------------------------------------------
// Kernel 0: W -> bf16 (tiny; L2-resident afterwards). grid 40 x 256.
// ---------------------------------------------------------------------------
__global__ __launch_bounds__(256)
void prep_w(const float* __restrict__ Wq, const float* __restrict__ Wk,
            const float* __restrict__ Wv)
{
    int idx = blockIdx.x * 256 + threadIdx.x;          // 0..10239
    int n = idx >> 5, cg = idx & 31;
    const float* row = (n < 32) ? Wq + n * C_
                     : (n < 64) ? Wk + (n - 32) * C_
                                : Wv + (n - 64) * C_;
    const float* p = row + cg * 8;
    uint4 o;
    o.x = pack_bf16(p[0], p[1]); o.y = pack_bf16(p[2], p[3]);
    o.z = pack_bf16(p[4], p[5]); o.w = pack_bf16(p[6], p[7]);
    g_wb4[idx] = o;
}

// ---------------------------------------------------------------------------
// Kernel 1: fused x-convert + QKV GEMM (bf16 mma.sync).
//   CTA = 128-pixel M-tile x full N=320 (5 chunks of 64). 256 threads.
//   Stage fp32 x slabs (64ch x 128pix, 528B rows, double buffered) via
//   cp.async, convert to swizzled bf16 A (4 x 16KB). B double-buffered.
// ---------------------------------------------------------------------------
#define XST_ROW 528                        // 132 floats per channel row
#define XST_SZ  (64 * XST_ROW)             // 33792 bytes per stage buffer
#define OFF_B   65536
#define OFF_X   131072
#define GEMM_SMEM (OFF_X + 2 * XST_SZ + 1024)   // ~199.7 KB

__global__ __launch_bounds__(256)
void qkv_mma_gemm(const float* __restrict__ x,
                  const float* __restrict__ bq, const float* __restrict__ bk,
                  const float* __restrict__ bv)
{
    extern __shared__ unsigned char dsm[];
    __shared__ float sbias[320];

    const int tid  = threadIdx.x;
    const int lane = tid & 31;
    const int wid  = tid >> 5;
    const int wm   = wid >> 1;          // 0..3 (M)
    const int wn   = wid & 1;           // 0..1 (N)
    const int pix0 = blockIdx.x * 128;
    const int b    = pix0 >> 12;
    const int hw0  = pix0 & 4095;

    unsigned char* base = (unsigned char*)(((uintptr_t)dsm + 1023) & ~(uintptr_t)1023);
    const uint32_t As_u = (uint32_t)__cvta_generic_to_shared(base);
    const uint32_t Bs_u = As_u + OFF_B;
    const uint32_t Xs_u = As_u + OFF_X;

    for (int i = tid; i < 320; i += 256)
        sbias[i] = (i < 32) ? bq[i] : (i < 64) ? bk[i - 32] : bv[i - 64];

    const float* xb = x + ((size_t)b << 20) + hw0;     // x[b][ch][hw0..]

    // --- issue x stage chunk kc into buffer buf ---
    #define ISSUE_X(kc, buf) do {                                             \
        uint32_t dst0 = Xs_u + (buf) * XST_SZ;                                \
        _Pragma("unroll")                                                     \
        for (int it = 0; it < 8; ++it) {                                      \
            int u = it * 256 + tid;                                           \
            int c = u >> 5, s = u & 31;                                       \
            cp16(dst0 + c * XST_ROW + s * 16,                                 \
                 xb + (size_t)((kc) * 64 + c) * HW_ + s * 4);                 \
        }                                                                     \
        asm volatile("cp.async.commit_group;" ::: "memory");                  \
    } while (0)

    #define ISSUE_B(nc, buf) do {                                             \
        const uint4* srcB = g_wb4 + (size_t)(nc) * 64 * 32;                   \
        uint32_t bb = Bs_u + (buf) * 32768;                                   \
        _Pragma("unroll")                                                     \
        for (int it = 0; it < 8; ++it) {                                      \
            int u = it * 256 + tid;                                           \
            int n = u >> 5, g = u & 31;                                       \
            cp16(bb + (g >> 3) * 8192 + SWZ(n * 128 + (g & 7) * 16), srcB + u);\
        }                                                                     \
        asm volatile("cp.async.commit_group;" ::: "memory");                  \
    } while (0)

    // convert stage buffer (fp32 [64ch][132f]) -> A chunk kc (bf16 swizzled)
    #define CONVERT(kc, buf) do {                                             \
        const float* xs = (const float*)(base + OFF_X + (buf) * XST_SZ);      \
        unsigned char* dA = base + (kc) * 16384;                              \
        const int p = tid & 127;                                              \
        const int hf = tid >> 7;                                              \
        _Pragma("unroll")                                                     \
        for (int t = 0; t < 16; ++t) {                                        \
            int c2 = hf * 16 + t;                                             \
            uint32_t w = pack_bf16(xs[(2 * c2) * 132 + p],                    \
                                   xs[(2 * c2 + 1) * 132 + p]);               \
            *(uint32_t*)(dA + SWZ(p * 128 + c2 * 4)) = w;                     \
        }                                                                     \
    } while (0)

    ISSUE_X(0, 0);                // group C0
    ISSUE_X(1, 1);                // C1
    ISSUE_B(0, 0);                // C2

    asm volatile("cp.async.wait_group 2;" ::: "memory");   // C0 done
    __syncthreads();
    CONVERT(0, 0);
    __syncthreads();
    ISSUE_X(2, 0);                // C3

    asm volatile("cp.async.wait_group 2;" ::: "memory");   // C0,C1 done
    __syncthreads();
    CONVERT(1, 1);
    __syncthreads();
    ISSUE_X(3, 1);                // C4

    asm volatile("cp.async.wait_group 1;" ::: "memory");   // ..C3 done (incl B0)
    __syncthreads();
    CONVERT(2, 0);
    __syncthreads();

    asm volatile("cp.async.wait_group 0;" ::: "memory");   // all done
    __syncthreads();
    CONVERT(3, 1);
    __syncthreads();

    // ldmatrix lane-address components
    const int a_row  = (lane & 15);
    const int a_koff = (lane >> 4) << 4;
    const int b_r    = (lane & 7);
    const int b_grp  = lane >> 3;
    const int b_nrow = ((b_grp >> 1) << 3) + b_r;
    const int b_koff = (b_grp & 1) << 4;

    for (int nc = 0; nc < 5; ++nc) {
        if (nc < 4) ISSUE_B(nc + 1, (nc + 1) & 1);
        const uint32_t Bcur = Bs_u + (nc & 1) * 32768;

        float acc[2][4][4];
        #pragma unroll
        for (int mi = 0; mi < 2; mi++)
            #pragma unroll
            for (int nj = 0; nj < 4; nj++)
                #pragma unroll
                for (int q = 0; q < 4; q++) acc[mi][nj][q] = 0.f;

        #pragma unroll
        for (int kt = 0; kt < 16; ++kt) {
            const int chunk = kt >> 2;
            const int kb    = (kt & 3) * 32;

            uint32_t af[2][4];
            #pragma unroll
            for (int mi = 0; mi < 2; mi++) {
                int row = wm * 32 + mi * 16 + a_row;
                uint32_t ad = As_u + chunk * 16384 + SWZ(row * 128 + kb + a_koff);
                asm volatile("ldmatrix.sync.aligned.m8n8.x4.shared.b16 {%0,%1,%2,%3}, [%4];"
                             : "=r"(af[mi][0]), "=r"(af[mi][1]), "=r"(af[mi][2]), "=r"(af[mi][3])
                             : "r"(ad));
            }
            uint32_t bf[2][4];
            #pragma unroll
            for (int njp = 0; njp < 2; njp++) {
                int n = wn * 32 + njp * 16 + b_nrow;
                uint32_t bd = Bcur + chunk * 8192 + SWZ(n * 128 + kb + b_koff);
                asm volatile("ldmatrix.sync.aligned.m8n8.x4.shared.b16 {%0,%1,%2,%3}, [%4];"
                             : "=r"(bf[njp][0]), "=r"(bf[njp][1]), "=r"(bf[njp][2]), "=r"(bf[njp][3])
                             : "r"(bd));
            }
            #pragma unroll
            for (int mi = 0; mi < 2; mi++)
                #pragma unroll
                for (int nj = 0; nj < 4; nj++) {
                    uint32_t b0 = bf[nj >> 1][(nj & 1) * 2 + 0];
                    uint32_t b1 = bf[nj >> 1][(nj & 1) * 2 + 1];
                    asm volatile(
                        "mma.sync.aligned.m16n8k16.row.col.f32.bf16.bf16.f32 "
                        "{%0,%1,%2,%3}, {%4,%5,%6,%7}, {%8,%9}, {%0,%1,%2,%3};"
                        : "+f"(acc[mi][nj][0]), "+f"(acc[mi][nj][1]),
                          "+f"(acc[mi][nj][2]), "+f"(acc[mi][nj][3])
                        : "r"(af[mi][0]), "r"(af[mi][1]), "r"(af[mi][2]), "r"(af[mi][3]),
                          "r"(b0), "r"(b1));
                }
        }

        // Epilogue: nc==0 -> fp32 q|k; nc>=1 -> bf16x2 v
        {
            const int colq = (lane & 3) * 2;
            const int rowq = lane >> 2;
            #pragma unroll
            for (int mi = 0; mi < 2; mi++) {
                int r0 = pix0 + wm * 32 + mi * 16 + rowq;
                #pragma unroll
                for (int nj = 0; nj < 4; nj++) {
                    int col = nc * 64 + wn * 32 + nj * 8 + colq;
                    float bs0 = sbias[col], bs1 = sbias[col + 1];
                    float v00 = acc[mi][nj][0] + bs0, v01 = acc[mi][nj][1] + bs1;
                    float v10 = acc[mi][nj][2] + bs0, v11 = acc[mi][nj][3] + bs1;
                    if (nc == 0) {
                        *(float2*)(g_qk + (size_t)r0 * 64 + col)       = make_float2(v00, v01);
                        *(float2*)(g_qk + (size_t)(r0 + 8) * 64 + col) = make_float2(v10, v11);
                    } else {
                        int vcol2 = (col - 64) >> 1;
                        g_vb[(size_t)r0 * 128 + vcol2]       = pack_bf16(v00, v01);
                        g_vb[(size_t)(r0 + 8) * 128 + vcol2] = pack_bf16(v10, v11);
                    }
                }
            }
        }

        if (nc < 4) {
            asm volatile("cp.async.wait_group 0;" ::: "memory");
            __syncthreads();
        }
    }
}

// ---------------------------------------------------------------------------
// Kernel 2: local 3x3 window attention + residual. q/k fp32, v bf16.
// ---------------------------------------------------------------------------
#define PTILE 32
#define KCOLS 34
#define VROW  66     // uint32 per (r,col) v row: 64 data + 2 pad (2-way bank max)

__global__ __launch_bounds__(256)
void attn_kernel(const float* __restrict__ x,
                 const float* __restrict__ gamma,
                 float* __restrict__ out)
{
    __shared__ uint32_t smem_u[3 * KCOLS * VROW];     // 6732 u32 = 26928 B
    __shared__ float se[PTILE * 9];

    float* sq = (float*)smem_u;                        // [32][33]
    float* sk = (float*)smem_u + PTILE * 33;           // [3][34][33]

    const int tid   = threadIdx.x;
    const int b     = blockIdx.y;
    const int h     = blockIdx.x >> 1;
    const int wbase = (blockIdx.x & 1) * PTILE;
    const int pixrow = b * HW_ + h * W_;
    const float g0 = gamma[0];

    // Phase 1: load q tile + k halo (fp32 from g_qk)
    for (int idx = tid; idx < PTILE * 32; idx += 256) {
        int p = idx >> 5, c = idx & 31;
        sq[p * 33 + c] = g_qk[(size_t)(pixrow + wbase + p) * 64 + c];
    }
    for (int idx = tid; idx < 3 * KCOLS * 32; idx += 256) {
        int c    = idx & 31;
        int rest = idx >> 5;
        int col  = rest % KCOLS;
        int r    = rest / KCOLS;
        int hh   = h + r - 1;
        int ww   = wbase + col - 1;
        float v = 0.f;
        if (hh >= 0 && hh < H_ && ww >= 0 && ww < W_)
            v = g_qk[(size_t)(b * HW_ + hh * W_ + ww) * 64 + 32 + c];
        sk[(r * KCOLS + col) * 33 + c] = v;
    }
    __syncthreads();

    // Energies (288 tasks)
    for (int task = tid; task < PTILE * 9; task += 256) {
        int p = task / 9, j = task % 9;
        int r = j / 3, dx = j % 3;
        const float* qp = sq + p * 33;
        const float* kp = sk + (r * KCOLS + p + dx) * 33;
        float e = 0.f;
        #pragma unroll
        for (int c = 0; c < 32; c++) e = fmaf(qp[c], kp[c], e);
        se[p * 9 + j] = e;
    }
    __syncthreads();

    // Softmax over 9 (OOB zeros stay in denominator, matching reference)
    if (tid < PTILE) {
        float e[9], m = -1e30f;
        #pragma unroll
        for (int j = 0; j < 9; j++) { e[j] = se[tid * 9 + j]; m = fmaxf(m, e[j]); }
        float s = 0.f;
        #pragma unroll
        for (int j = 0; j < 9; j++) { e[j] = expf(e[j] - m); s += e[j]; }
        float inv = 1.f / s;
        #pragma unroll
        for (int j = 0; j < 9; j++) se[tid * 9 + j] = e[j] * inv;
    }
    __syncthreads();

    // Phase 3: v accumulation, 2 chunks of 128 bf16 channels
    const int p  = tid & 31;
    const int cg = tid >> 5;          // 0..7 -> 16 channels each
    float a[9];
    #pragma unroll
    for (int j = 0; j < 9; j++) a[j] = se[p * 9 + j];

    int basej[9];
    #pragma unroll
    for (int j = 0; j < 9; j++)
        basej[j] = ((j / 3) * KCOLS + p + (j % 3)) * VROW + cg * 8;

    for (int chunk = 0; chunk < 2; ++chunk) {
        __syncthreads();
        // load v halo chunk: 3*34 cols x 32 uint2 (=64 u32) each
        uint2* sv2 = (uint2*)smem_u;
        for (int idx = tid; idx < 3 * KCOLS * 32; idx += 256) {
            int c2   = idx & 31;
            int rest = idx >> 5;
            int col  = rest % KCOLS;
            int r    = rest / KCOLS;
            int hh   = h + r - 1;
            int ww   = wbase + col - 1;
            uint2 v = make_uint2(0u, 0u);
            if (hh >= 0 && hh < H_ && ww >= 0 && ww < W_)
                v = *(const uint2*)(g_vb + (size_t)(b * HW_ + hh * W_ + ww) * 128
                                    + chunk * 64 + c2 * 2);
            sv2[(r * KCOLS + col) * 33 + c2] = v;
        }
        __syncthreads();

        float acc[16];
        #pragma unroll
        for (int i = 0; i < 16; i++) acc[i] = 0.f;
        #pragma unroll
        for (int j = 0; j < 9; j++) {
            const uint32_t* svp = smem_u + basej[j];
            float aj = a[j];
            #pragma unroll
            for (int u = 0; u < 8; u++) {
                uint32_t w = svp[u];
                float2 f = __bfloat1622float2(*(const __nv_bfloat162*)&w);
                acc[2 * u + 0] = fmaf(aj, f.x, acc[2 * u + 0]);
                acc[2 * u + 1] = fmaf(aj, f.y, acc[2 * u + 1]);
            }
        }

        // out = gamma*o + x  (coalesced along w)
        #pragma unroll
        for (int i = 0; i < 16; i++) {
            int cglob = chunk * 128 + cg * 16 + i;
            size_t xi = ((size_t)(b * C_ + cglob)) * HW_ + h * W_ + wbase + p;
            out[xi] = fmaf(g0, acc[i], x[xi]);
        }
    }
}

// ---------------------------------------------------------------------------
extern "C" void kernel_launch(void* const* d_in, const int* in_sizes, int n_in,
                              void* d_out, int out_size)
{
    const float* x     = (const float*)d_in[0];
    const float* Wq    = (const float*)d_in[1];
    const float* bq    = (const float*)d_in[2];
    const float* Wk    = (const float*)d_in[3];
    const float* bk    = (const float*)d_in[4];
    const float* Wv    = (const float*)d_in[5];
    const float* bv    = (const float*)d_in[6];
    const float* gamma = (const float*)d_in[7];
    float* out = (float*)d_out;

    cudaFuncSetAttribute(qkv_mma_gemm, cudaFuncAttributeMaxDynamicSharedMemorySize, GEMM_SMEM);

    prep_w<<<40, 256>>>(Wq, Wk, Wv);
    qkv_mma_gemm<<<256, 256, GEMM_SMEM>>>(x, bq, bk, bv);

    dim3 agrid(H_ * 2, B_);
    attn_kernel<<<agrid, 256>>>(x, gamma, out);
}